// round 4
// baseline (speedup 1.0000x reference)
#include <cuda_runtime.h>
#include <math.h>

#define BATCH 8
#define NN 262144
#define PRE 6000
#define PROP 1000
#define SEL_CAP 8192
#define CMASK 1024
#define MWORDS (CMASK / 32)

// ---------------- scratch ----------------
__device__ int                g_h16[BATCH * 65536];           // 2 MB (zero-init at load; select16 re-zeros)
__device__ unsigned int       g_thr[BATCH];
__device__ int                g_cnt[BATCH];                   // reset by select16 before compact
__device__ unsigned long long g_sel[BATCH * SEL_CAP];
__device__ float4             g_boxes[BATCH * PRE];
__device__ unsigned int       g_mask[BATCH * CMASK * MWORDS]; // 1 MB

__device__ __forceinline__ unsigned fkey(float f) {
    unsigned u = __float_as_uint(f);
    return u ^ (((unsigned)((int)u >> 31)) | 0x80000000u);
}

// ---------------- pass 1: 16-bit histogram of score keys ----------------
// grid (128, BATCH) x 256 threads; 4 float4 per thread, prefetched
__global__ void extract_hist16_k(const float* __restrict__ probs) {
    int tid = threadIdx.x, b = blockIdx.y;
    const float4* p4 = (const float4*)probs + (size_t)b * (NN / 2);
    int* h = &g_h16[b * 65536];
    float4 v[4];
    int f0 = blockIdx.x * 1024 + tid;
#pragma unroll
    for (int t = 0; t < 4; t++) v[t] = p4[f0 + t * 256];
#pragma unroll
    for (int t = 0; t < 4; t++) {
        atomicAdd(&h[fkey(v[t].y) >> 16], 1);
        atomicAdd(&h[fkey(v[t].w) >> 16], 1);
    }
}

// ---------------- select 16-bit threshold bin; re-zero hist; reset cnt ----------------
__global__ void select16_k() {
    __shared__ int part[1024];
    int tid = threadIdx.x, b = blockIdx.x;
    int* h = &g_h16[b * 65536];
    int s = 0, base = tid * 64;
    int loc[64];
#pragma unroll 8
    for (int q = 0; q < 64; q++) { loc[q] = h[base + q]; s += loc[q]; }
    part[tid] = s;
    // re-zero for next replay (we have the values in registers/smem now)
#pragma unroll 8
    for (int q = 0; q < 64; q++) h[base + q] = 0;
    if (tid == 0) g_cnt[b] = 0;
    __syncthreads();
    if (tid == 0) {
        int acc = 0, t = 1023;
        for (; t > 0; t--) {
            int c = part[t];
            if (acc + c >= PRE) break;
            acc += c;
        }
        part[1023] = t;            // broadcast chosen coarse chunk
    }
    __syncthreads();
    int t = part[1023];
    if (tid == t) {
        // recompute suffix above chunk t
        int acc = 0;
        for (int q = 1023; q > t; q--) acc += part[q];
        int bin = 63;
        for (; bin > 0; bin--) {
            int c = loc[bin];
            if (acc + c >= PRE) break;
            acc += c;
        }
        g_thr[b] = ((unsigned)(t * 64 + bin)) << 16;
    }
}

// ---------------- compact all keys >= threshold (re-reads probs from L2) ----------------
// grid (64, BATCH) x 256 threads; 8 float4 per thread, prefetched before atomics
__global__ void compact_k(const float* __restrict__ probs) {
    int tid = threadIdx.x, b = blockIdx.y;
    unsigned T = g_thr[b];
    const float4* p4 = (const float4*)probs + (size_t)b * (NN / 2);
    int f0 = blockIdx.x * 2048 + tid;
    float4 v[8];
#pragma unroll
    for (int t = 0; t < 8; t++) v[t] = p4[f0 + t * 256];
#pragma unroll
    for (int t = 0; t < 8; t++) {
        int f = f0 + t * 256;
        unsigned k0 = fkey(v[t].y), k1 = fkey(v[t].w);
        if (k0 >= T) {
            int pos = atomicAdd(&g_cnt[b], 1);
            if (pos < SEL_CAP)
                g_sel[b * SEL_CAP + pos] =
                    (((unsigned long long)(~k0)) << 32) | (unsigned)(f * 2);
        }
        if (k1 >= T) {
            int pos = atomicAdd(&g_cnt[b], 1);
            if (pos < SEL_CAP)
                g_sel[b * SEL_CAP + pos] =
                    (((unsigned long long)(~k1)) << 32) | (unsigned)(f * 2 + 1);
        }
    }
}

// ---------------- sort stage A: independent 2048-segment bitonic sorts ----------------
// grid (4, BATCH) x 1024 threads. Segment s sorted ascending iff (s & 1)==0
// (bitonic invariant: block at offset p sorted ascending iff (p & k)==0 after stage k).
__global__ void __launch_bounds__(1024, 1) sortA_k() {
    __shared__ unsigned long long a[2048];
    int tid = threadIdx.x, seg = blockIdx.x, b = blockIdx.y;
    int cnt = g_cnt[b];
    if (cnt > SEL_CAP) cnt = SEL_CAP;
    int base = seg * 2048;
    unsigned long long* gs = &g_sel[b * SEL_CAP];
#pragma unroll
    for (int e = 0; e < 2; e++) {
        int i = base + tid + e * 1024;
        a[tid + e * 1024] = (i < cnt) ? gs[i] : 0xFFFFFFFFFFFFFFFFull;
    }
    __syncthreads();
    bool dir = ((seg & 1) == 0);
    for (int k = 2; k <= 2048; k <<= 1) {
        for (int j = k >> 1; j > 0; j >>= 1) {
            int i = ((tid & ~(j - 1)) << 1) | (tid & (j - 1));
            int ix = i | j;
            unsigned long long x = a[i], y = a[ix];
            bool up = (((i & k) == 0) == dir);
            if ((x > y) == up) { a[i] = y; a[ix] = x; }
            __syncthreads();
        }
    }
#pragma unroll
    for (int e = 0; e < 2; e++) gs[base + tid + e * 1024] = a[tid + e * 1024];
}

// ---------------- sort stage B: k=4096,8192 merges + decode ----------------
__device__ __forceinline__ void cswap(unsigned long long& x, unsigned long long& y, bool up) {
    if ((x > y) == up) { unsigned long long t = x; x = y; y = t; }
}

__global__ void __launch_bounds__(1024, 1)
sortB_decode_k(const float* __restrict__ bbox, const float* __restrict__ anchors) {
    extern __shared__ unsigned long long a[];
    int tid = threadIdx.x, b = blockIdx.x;
    unsigned long long* gs = &g_sel[b * SEL_CAP];
    for (int i = tid; i < SEL_CAP; i += 1024) a[i] = gs[i];
    __syncthreads();

    unsigned long long v[8];
    int rbase = tid * 8;

#pragma unroll
    for (int k = 4096; k <= SEL_CAP; k <<= 1) {
        for (int j = k >> 1; j >= 8; j >>= 1) {
#pragma unroll 4
            for (int m = tid; m < SEL_CAP / 2; m += 1024) {
                int i = ((m & ~(j - 1)) << 1) | (m & (j - 1));
                int ix = i | j;
                unsigned long long x = a[i], y = a[ix];
                if ((x > y) == ((i & k) == 0)) { a[i] = y; a[ix] = x; }
            }
            __syncthreads();
        }
        bool up = ((rbase & k) == 0);
#pragma unroll
        for (int e = 0; e < 8; e++) v[e] = a[rbase + e];
#pragma unroll
        for (int j = 4; j > 0; j >>= 1) {
#pragma unroll
            for (int e = 0; e < 8; e++) {
                int ex = e ^ j;
                if (ex > e) cswap(v[e], v[ex], up);
            }
        }
#pragma unroll
        for (int e = 0; e < 8; e++) a[rbase + e] = v[e];
        __syncthreads();
    }

    // decode top PRE boxes
    for (int r = tid; r < PRE; r += 1024) {
        unsigned idx = (unsigned)a[r];
        float4 A = ((const float4*)anchors)[(size_t)b * NN + idx];
        float4 D = ((const float4*)bbox)[(size_t)b * NN + idx];
        float y1 = A.x, x1 = A.y, y2 = A.z, x2 = A.w;
        float h = __fsub_rn(y2, y1), w = __fsub_rn(x2, x1);
        float cy = __fadd_rn(y1, __fmul_rn(0.5f, h));
        float cx = __fadd_rn(x1, __fmul_rn(0.5f, w));
        float d0 = __fmul_rn(D.x, 0.1f), d1 = __fmul_rn(D.y, 0.1f);
        float d2 = __fmul_rn(D.z, 0.2f), d3 = __fmul_rn(D.w, 0.2f);
        cy = __fadd_rn(cy, __fmul_rn(d0, h));
        cx = __fadd_rn(cx, __fmul_rn(d1, w));
        h = __fmul_rn(h, expf(d2));
        w = __fmul_rn(w, expf(d3));
        float ny1 = __fsub_rn(cy, __fmul_rn(0.5f, h));
        float nx1 = __fsub_rn(cx, __fmul_rn(0.5f, w));
        float ny2 = __fadd_rn(cy, __fmul_rn(0.5f, h));
        float nx2 = __fadd_rn(cx, __fmul_rn(0.5f, w));
        ny1 = fminf(fmaxf(ny1, 0.f), 1.f);
        nx1 = fminf(fmaxf(nx1, 0.f), 1.f);
        ny2 = fminf(fmaxf(ny2, 0.f), 1.f);
        nx2 = fminf(fmaxf(nx2, 0.f), 1.f);
        g_boxes[b * PRE + r] = make_float4(ny1, nx1, ny2, nx2);
    }
}

// ---------------- suppression IoU ----------------
__device__ __forceinline__ int suppresses(float4 s, float sArea, float4 c) {
    float iy1 = fmaxf(c.x, s.x), ix1 = fmaxf(c.y, s.y);
    float iy2 = fminf(c.z, s.z), ix2 = fminf(c.w, s.w);
    float ih = fmaxf(__fsub_rn(iy2, iy1), 0.f);
    float iw = fmaxf(__fsub_rn(ix2, ix1), 0.f);
    float inter = __fmul_rn(ih, iw);
    float areaC = __fmul_rn(__fsub_rn(c.z, c.x), __fsub_rn(c.w, c.y));
    float uni = __fsub_rn(__fadd_rn(sArea, areaC), inter);
    float iou = __fdiv_rn(inter, fmaxf(uni, 1e-10f));
    return iou > 0.7f;
}

// ---------------- IoU suppression bit-matrix ----------------
__global__ void iou_mask_k() {
    int b = blockIdx.y;
    int w = blockIdx.x * 256 + threadIdx.x;
    int i = w >> 5;
    int wj = w & (MWORDS - 1);
    float4 s = g_boxes[b * PRE + i];
    float sArea = __fmul_rn(__fsub_rn(s.z, s.x), __fsub_rn(s.w, s.y));
    unsigned bits = 0;
    int basej = wj * 32;
    if (basej + 31 > i) {
#pragma unroll 8
        for (int bb = 0; bb < 32; bb++) {
            int j = basej + bb;
            if (j > i) {
                float4 c = g_boxes[b * PRE + j];
                if (suppresses(s, sArea, c)) bits |= (1u << bb);
            }
        }
    }
    g_mask[(b * CMASK + i) * MWORDS + wj] = bits;
}

// ---------------- block-sequential parallel NMS resolve ----------------
#define SMEM_RESOLVE (CMASK * MWORDS * 4 + 32 * 4 + 32 * 4 + 33 * 4 + PROP * 4 + 32)

__global__ void __launch_bounds__(1024, 1) nms_resolve_k(float* __restrict__ out) {
    extern __shared__ unsigned sm[];
    unsigned* smask  = sm;                          // CMASK*MWORDS
    unsigned* supArr = sm + CMASK * MWORDS;         // 32
    unsigned* awords = supArr + 32;                 // 32
    int* wpref       = (int*)(awords + 32);         // 33
    int* selids      = wpref + 33;                  // PROP

    int tid = threadIdx.x, b = blockIdx.x;

    const unsigned* gm = &g_mask[b * CMASK * MWORDS];
#pragma unroll
    for (int i = tid; i < CMASK * MWORDS; i += 1024) smask[i] = gm[i];
    if (tid < 32) { supArr[tid] = 0; awords[tid] = 0xFFFFFFFFu; }
    __syncthreads();

    for (int B = 0; B < MWORDS; B++) {
        unsigned contrib = 0;
        if (tid < B * 32) {
            if ((awords[tid >> 5] >> (tid & 31)) & 1u)
                contrib = smask[tid * MWORDS + B];
        }
        contrib = __reduce_or_sync(0xFFFFFFFFu, contrib);
        if ((tid & 31) == 0 && contrib) atomicOr(&supArr[B], contrib);
        __syncthreads();
        if (tid < 32) {
            unsigned myrow = smask[(B * 32 + tid) * MWORDS + B];
            unsigned aliveB = ~supArr[B];
            unsigned candm = __ballot_sync(0xFFFFFFFFu, myrow != 0);
            while (true) {
                unsigned act = candm & aliveB;
                if (!act) break;
                int bs = __ffs(act) - 1;
                unsigned rowW = __shfl_sync(0xFFFFFFFFu, myrow, bs);
                aliveB &= ~rowW;
                candm &= ~(1u << bs);
            }
            if (tid == 0) awords[B] = aliveB;
        }
        __syncthreads();
    }

    if (tid == 0) {
        int acc = 0;
        for (int wq = 0; wq < 32; wq++) { wpref[wq] = acc; acc += __popc(awords[wq]); }
        wpref[32] = acc;
    }
    __syncthreads();
    if (tid < CMASK) {
        unsigned wv = awords[tid >> 5];
        if ((wv >> (tid & 31)) & 1u) {
            int rank = wpref[tid >> 5] + __popc(wv & ((1u << (tid & 31)) - 1u));
            if (rank < PROP) selids[rank] = tid;
        }
    }
    __syncthreads();
    int k = wpref[32];
    if (k > PROP) k = PROP;

    // fallback beyond CMASK (rare)
    if (k < PROP) {
        float4 mysel = make_float4(0.f, 0.f, 0.f, 0.f);
        float myarea = 0.f;
        if (tid < k) {
            mysel = g_boxes[b * PRE + selids[tid]];
            myarea = __fmul_rn(__fsub_rn(mysel.z, mysel.x), __fsub_rn(mysel.w, mysel.y));
        }
        __syncthreads();
        for (int cand = CMASK; cand < PRE; cand++) {
            float4 c = g_boxes[b * PRE + cand];
            int pred = 0;
            if (tid < k) pred = suppresses(mysel, myarea, c);
            int rej = __syncthreads_or(pred);
            if (!rej) {
                if (tid == k) {
                    mysel = c;
                    myarea = __fmul_rn(__fsub_rn(c.z, c.x), __fsub_rn(c.w, c.y));
                }
                if (tid == 0) selids[k] = cand;
                k++;
                if (k == PROP) break;
            }
        }
        __syncthreads();
    }

    float4* outp = (float4*)out + (size_t)b * PROP;
    if (tid < PROP) {
        if (tid < k) outp[tid] = g_boxes[b * PRE + selids[tid]];
        else         outp[tid] = make_float4(0.f, 0.f, 0.f, 0.f);
    }
}

// ---------------- launch ----------------
extern "C" void kernel_launch(void* const* d_in, const int* in_sizes, int n_in,
                              void* d_out, int out_size) {
    const float* probs   = (const float*)d_in[0];
    const float* bbox    = (const float*)d_in[1];
    const float* anchors = (const float*)d_in[2];
    float* out = (float*)d_out;

    cudaFuncSetAttribute(sortB_decode_k, cudaFuncAttributeMaxDynamicSharedMemorySize, SEL_CAP * 8);
    cudaFuncSetAttribute(nms_resolve_k,  cudaFuncAttributeMaxDynamicSharedMemorySize, SMEM_RESOLVE);

    dim3 ge(128, BATCH);
    extract_hist16_k<<<ge, 256>>>(probs);
    select16_k<<<BATCH, 1024>>>();
    dim3 gc(64, BATCH);
    compact_k<<<gc, 256>>>(probs);
    dim3 ga(4, BATCH);
    sortA_k<<<ga, 1024>>>();
    sortB_decode_k<<<BATCH, 1024, SEL_CAP * 8>>>(bbox, anchors);
    dim3 gi((CMASK * MWORDS) / 256, BATCH);
    iou_mask_k<<<gi, 256>>>();
    nms_resolve_k<<<BATCH, 1024, SMEM_RESOLVE>>>(out);
}

// round 5
// speedup vs baseline: 1.1718x; 1.1718x over previous
#include <cuda_runtime.h>
#include <math.h>

#define BATCH 8
#define NN 262144
#define PRE 6000
#define PROP 1000
#define SEL_CAP 8192
#define CMASK 1024
#define MWORDS (CMASK / 32)

// ---------------- scratch ----------------
__device__ int                g_h16[BATCH * 65536];           // zero-init; select16 re-zeros
__device__ unsigned int       g_thr[BATCH];
__device__ int                g_cnt[BATCH];                   // reset by select16
__device__ unsigned long long g_sel[BATCH * SEL_CAP];
__device__ float4             g_boxes[BATCH * PRE];
__device__ unsigned int       g_mask[BATCH * CMASK * MWORDS];

__device__ __forceinline__ unsigned fkey(float f) {
    unsigned u = __float_as_uint(f);
    return u ^ (((unsigned)((int)u >> 31)) | 0x80000000u);
}

// ---------------- pass 1: 16-bit histogram of score keys ----------------
__global__ void extract_hist16_k(const float* __restrict__ probs) {
    int tid = threadIdx.x, b = blockIdx.y;
    const float4* p4 = (const float4*)probs + (size_t)b * (NN / 2);
    int* h = &g_h16[b * 65536];
    float4 v[4];
    int f0 = blockIdx.x * 1024 + tid;
#pragma unroll
    for (int t = 0; t < 4; t++) v[t] = p4[f0 + t * 256];
#pragma unroll
    for (int t = 0; t < 4; t++) {
        atomicAdd(&h[fkey(v[t].y) >> 16], 1);
        atomicAdd(&h[fkey(v[t].w) >> 16], 1);
    }
}

// ---------------- select threshold bin (parallel suffix scan, no spills) ----------------
__global__ void __launch_bounds__(1024, 1) select16_k() {
    __shared__ int part[1024];
    __shared__ int save[64];
    __shared__ int chunkT;
    int tid = threadIdx.x, b = blockIdx.x;
    int* h = &g_h16[b * 65536];
    const int4* h4 = (const int4*)h;

    // per-thread sum of its 64 bins (16 int4 loads, no retention)
    int s = 0;
#pragma unroll
    for (int q = 0; q < 16; q++) {
        int4 v = h4[tid * 16 + q];
        s += v.x + v.y + v.z + v.w;
    }
    int val = s;
    part[tid] = val;
    __syncthreads();
    // inclusive suffix scan: part[t] = sum_{q>=t} sums
    for (int off = 1; off < 1024; off <<= 1) {
        int add = (tid + off < 1024) ? part[tid + off] : 0;
        __syncthreads();
        val += add;
        part[tid] = val;
        __syncthreads();
    }
    // coarse chunk: largest t with suffix[t] >= PRE
    if (part[tid] >= PRE && (tid == 1023 || part[tid + 1] < PRE)) chunkT = tid;
    __syncthreads();
    int t = chunkT;
    // stash the winning chunk's bins before zeroing
    if (tid < 64) save[tid] = h[t * 64 + tid];
    __syncthreads();
    // re-zero histogram for next replay; reset cnt
    int4 z = make_int4(0, 0, 0, 0);
#pragma unroll
    for (int q = 0; q < 16; q++) ((int4*)h)[tid * 16 + q] = z;
    if (tid == 0) {
        g_cnt[b] = 0;
        int acc = (t < 1023) ? part[t + 1] : 0;
        int bin = 63;
        for (; bin > 0; bin--) {
            int c = save[bin];
            if (acc + c >= PRE) break;
            acc += c;
        }
        g_thr[b] = ((unsigned)(t * 64 + bin)) << 16;
    }
}

// ---------------- compact all keys >= threshold ----------------
__global__ void compact_k(const float* __restrict__ probs) {
    int tid = threadIdx.x, b = blockIdx.y;
    unsigned T = g_thr[b];
    const float4* p4 = (const float4*)probs + (size_t)b * (NN / 2);
    int f0 = blockIdx.x * 2048 + tid;
    float4 v[8];
#pragma unroll
    for (int t = 0; t < 8; t++) v[t] = p4[f0 + t * 256];
#pragma unroll
    for (int t = 0; t < 8; t++) {
        int f = f0 + t * 256;
        unsigned k0 = fkey(v[t].y), k1 = fkey(v[t].w);
        if (k0 >= T) {
            int pos = atomicAdd(&g_cnt[b], 1);
            if (pos < SEL_CAP)
                g_sel[b * SEL_CAP + pos] =
                    (((unsigned long long)(~k0)) << 32) | (unsigned)(f * 2);
        }
        if (k1 >= T) {
            int pos = atomicAdd(&g_cnt[b], 1);
            if (pos < SEL_CAP)
                g_sel[b * SEL_CAP + pos] =
                    (((unsigned long long)(~k1)) << 32) | (unsigned)(f * 2 + 1);
        }
    }
}

// ---------------- monolithic register-batched bitonic sort + decode ----------------
__device__ __forceinline__ void cswap(unsigned long long& x, unsigned long long& y, bool up) {
    if ((x > y) == up) { unsigned long long t = x; x = y; y = t; }
}

__global__ void __launch_bounds__(1024, 1)
sort_decode_k(const float* __restrict__ bbox, const float* __restrict__ anchors) {
    extern __shared__ unsigned long long a[];
    int tid = threadIdx.x, b = blockIdx.x;
    int cnt = g_cnt[b];
    if (cnt > SEL_CAP) cnt = SEL_CAP;
    for (int i = tid; i < SEL_CAP; i += 1024)
        a[i] = (i < cnt) ? g_sel[b * SEL_CAP + i] : 0xFFFFFFFFFFFFFFFFull;
    __syncthreads();

    unsigned long long v[8];
    int base = tid * 8;

#pragma unroll
    for (int e = 0; e < 8; e++) v[e] = a[base + e];
#pragma unroll
    for (int k = 2; k <= 8; k <<= 1) {
#pragma unroll
        for (int j = k >> 1; j > 0; j >>= 1) {
#pragma unroll
            for (int e = 0; e < 8; e++) {
                int ex = e ^ j;
                if (ex > e) cswap(v[e], v[ex], ((base + e) & k) == 0);
            }
        }
    }
#pragma unroll
    for (int e = 0; e < 8; e++) a[base + e] = v[e];
    __syncthreads();

    for (int k = 16; k <= SEL_CAP; k <<= 1) {
        for (int j = k >> 1; j >= 8; j >>= 1) {
#pragma unroll 4
            for (int m = tid; m < SEL_CAP / 2; m += 1024) {
                int i = ((m & ~(j - 1)) << 1) | (m & (j - 1));
                int ix = i | j;
                unsigned long long x = a[i], y = a[ix];
                if ((x > y) == ((i & k) == 0)) { a[i] = y; a[ix] = x; }
            }
            __syncthreads();
        }
        bool up = ((base & k) == 0);
#pragma unroll
        for (int e = 0; e < 8; e++) v[e] = a[base + e];
#pragma unroll
        for (int j = 4; j > 0; j >>= 1) {
#pragma unroll
            for (int e = 0; e < 8; e++) {
                int ex = e ^ j;
                if (ex > e) cswap(v[e], v[ex], up);
            }
        }
#pragma unroll
        for (int e = 0; e < 8; e++) a[base + e] = v[e];
        __syncthreads();
    }

    for (int r = tid; r < PRE; r += 1024) {
        unsigned idx = (unsigned)a[r];
        float4 A = ((const float4*)anchors)[(size_t)b * NN + idx];
        float4 D = ((const float4*)bbox)[(size_t)b * NN + idx];
        float y1 = A.x, x1 = A.y, y2 = A.z, x2 = A.w;
        float h = __fsub_rn(y2, y1), w = __fsub_rn(x2, x1);
        float cy = __fadd_rn(y1, __fmul_rn(0.5f, h));
        float cx = __fadd_rn(x1, __fmul_rn(0.5f, w));
        float d0 = __fmul_rn(D.x, 0.1f), d1 = __fmul_rn(D.y, 0.1f);
        float d2 = __fmul_rn(D.z, 0.2f), d3 = __fmul_rn(D.w, 0.2f);
        cy = __fadd_rn(cy, __fmul_rn(d0, h));
        cx = __fadd_rn(cx, __fmul_rn(d1, w));
        h = __fmul_rn(h, expf(d2));
        w = __fmul_rn(w, expf(d3));
        float ny1 = __fsub_rn(cy, __fmul_rn(0.5f, h));
        float nx1 = __fsub_rn(cx, __fmul_rn(0.5f, w));
        float ny2 = __fadd_rn(cy, __fmul_rn(0.5f, h));
        float nx2 = __fadd_rn(cx, __fmul_rn(0.5f, w));
        ny1 = fminf(fmaxf(ny1, 0.f), 1.f);
        nx1 = fminf(fmaxf(nx1, 0.f), 1.f);
        ny2 = fminf(fmaxf(ny2, 0.f), 1.f);
        nx2 = fminf(fmaxf(nx2, 0.f), 1.f);
        g_boxes[b * PRE + r] = make_float4(ny1, nx1, ny2, nx2);
    }
}

// ---------------- suppression IoU (exact, used by fallback) ----------------
__device__ __forceinline__ int suppresses(float4 s, float sArea, float4 c) {
    float iy1 = fmaxf(c.x, s.x), ix1 = fmaxf(c.y, s.y);
    float iy2 = fminf(c.z, s.z), ix2 = fminf(c.w, s.w);
    float ih = fmaxf(__fsub_rn(iy2, iy1), 0.f);
    float iw = fmaxf(__fsub_rn(ix2, ix1), 0.f);
    float inter = __fmul_rn(ih, iw);
    float areaC = __fmul_rn(__fsub_rn(c.z, c.x), __fsub_rn(c.w, c.y));
    float uni = __fsub_rn(__fadd_rn(sArea, areaC), inter);
    float iou = __fdiv_rn(inter, fmaxf(uni, 1e-10f));
    return iou > 0.7f;
}

// ---------------- IoU bit-matrix: warp-per-word, lane-per-pair, ballot ----------------
// grid (1024, BATCH) x 1024 threads: block = 32 warps = 32 words
__global__ void iou_mask_k() {
    int b = blockIdx.y;
    int warpId = threadIdx.x >> 5, lane = threadIdx.x & 31;
    int W = blockIdx.x * 32 + warpId;   // word index in [0, CMASK*MWORDS)
    int i = W >> 5;                      // suppressor row
    int wj = W & (MWORDS - 1);
    int j = wj * 32 + lane;              // suppressed candidate (lane-coalesced)
    const float4* bx = &g_boxes[(size_t)b * PRE];
    float4 s = bx[i];                    // broadcast across warp
    int bit = 0;
    if (j > i) {
        float4 c = bx[j];                // coalesced
        float iy1 = fmaxf(c.x, s.x), ix1 = fmaxf(c.y, s.y);
        float iy2 = fminf(c.z, s.z), ix2 = fminf(c.w, s.w);
        if (iy2 > iy1 && ix2 > ix1) {    // else IoU is exactly 0
            float ih = __fsub_rn(iy2, iy1);
            float iw = __fsub_rn(ix2, ix1);
            float inter = __fmul_rn(ih, iw);
            float sA = __fmul_rn(__fsub_rn(s.z, s.x), __fsub_rn(s.w, s.y));
            float cA = __fmul_rn(__fsub_rn(c.z, c.x), __fsub_rn(c.w, c.y));
            float uni = __fsub_rn(__fadd_rn(sA, cA), inter);
            float iou = __fdiv_rn(inter, fmaxf(uni, 1e-10f));
            bit = (iou > 0.7f);
        }
    }
    unsigned word = __ballot_sync(0xFFFFFFFFu, bit);
    if (lane == 0) g_mask[((size_t)b * CMASK + i) * MWORDS + wj] = word;
}

// ---------------- block-sequential parallel NMS resolve ----------------
#define SMEM_RESOLVE (CMASK * MWORDS * 4 + 32 * 4 + 32 * 4 + 33 * 4 + PROP * 4 + 32)

__global__ void __launch_bounds__(1024, 1) nms_resolve_k(float* __restrict__ out) {
    extern __shared__ unsigned sm[];
    unsigned* smask  = sm;
    unsigned* supArr = sm + CMASK * MWORDS;
    unsigned* awords = supArr + 32;
    int* wpref       = (int*)(awords + 32);
    int* selids      = wpref + 33;

    int tid = threadIdx.x, b = blockIdx.x;

    const unsigned* gm = &g_mask[(size_t)b * CMASK * MWORDS];
#pragma unroll
    for (int i = tid; i < CMASK * MWORDS; i += 1024) smask[i] = gm[i];
    if (tid < 32) { supArr[tid] = 0; awords[tid] = 0xFFFFFFFFu; }
    __syncthreads();

    for (int B = 0; B < MWORDS; B++) {
        unsigned contrib = 0;
        if (tid < B * 32) {
            if ((awords[tid >> 5] >> (tid & 31)) & 1u)
                contrib = smask[tid * MWORDS + B];
        }
        contrib = __reduce_or_sync(0xFFFFFFFFu, contrib);
        if ((tid & 31) == 0 && contrib) atomicOr(&supArr[B], contrib);
        __syncthreads();
        if (tid < 32) {
            unsigned myrow = smask[(B * 32 + tid) * MWORDS + B];
            unsigned aliveB = ~supArr[B];
            unsigned candm = __ballot_sync(0xFFFFFFFFu, myrow != 0);
            while (true) {
                unsigned act = candm & aliveB;
                if (!act) break;
                int bs = __ffs(act) - 1;
                unsigned rowW = __shfl_sync(0xFFFFFFFFu, myrow, bs);
                aliveB &= ~rowW;
                candm &= ~(1u << bs);
            }
            if (tid == 0) awords[B] = aliveB;
        }
        __syncthreads();
    }

    if (tid == 0) {
        int acc = 0;
        for (int wq = 0; wq < 32; wq++) { wpref[wq] = acc; acc += __popc(awords[wq]); }
        wpref[32] = acc;
    }
    __syncthreads();
    if (tid < CMASK) {
        unsigned wv = awords[tid >> 5];
        if ((wv >> (tid & 31)) & 1u) {
            int rank = wpref[tid >> 5] + __popc(wv & ((1u << (tid & 31)) - 1u));
            if (rank < PROP) selids[rank] = tid;
        }
    }
    __syncthreads();
    int k = wpref[32];
    if (k > PROP) k = PROP;

    // fallback beyond CMASK (few iterations expected)
    if (k < PROP) {
        float4 mysel = make_float4(0.f, 0.f, 0.f, 0.f);
        float myarea = 0.f;
        if (tid < k) {
            mysel = g_boxes[b * PRE + selids[tid]];
            myarea = __fmul_rn(__fsub_rn(mysel.z, mysel.x), __fsub_rn(mysel.w, mysel.y));
        }
        __syncthreads();
        for (int cand = CMASK; cand < PRE; cand++) {
            float4 c = g_boxes[b * PRE + cand];
            int pred = 0;
            if (tid < k) pred = suppresses(mysel, myarea, c);
            int rej = __syncthreads_or(pred);
            if (!rej) {
                if (tid == k) {
                    mysel = c;
                    myarea = __fmul_rn(__fsub_rn(c.z, c.x), __fsub_rn(c.w, c.y));
                }
                if (tid == 0) selids[k] = cand;
                k++;
                if (k == PROP) break;
            }
        }
        __syncthreads();
    }

    float4* outp = (float4*)out + (size_t)b * PROP;
    if (tid < PROP) {
        if (tid < k) outp[tid] = g_boxes[b * PRE + selids[tid]];
        else         outp[tid] = make_float4(0.f, 0.f, 0.f, 0.f);
    }
}

// ---------------- launch ----------------
extern "C" void kernel_launch(void* const* d_in, const int* in_sizes, int n_in,
                              void* d_out, int out_size) {
    const float* probs   = (const float*)d_in[0];
    const float* bbox    = (const float*)d_in[1];
    const float* anchors = (const float*)d_in[2];
    float* out = (float*)d_out;

    cudaFuncSetAttribute(sort_decode_k, cudaFuncAttributeMaxDynamicSharedMemorySize, SEL_CAP * 8);
    cudaFuncSetAttribute(nms_resolve_k, cudaFuncAttributeMaxDynamicSharedMemorySize, SMEM_RESOLVE);

    dim3 ge(128, BATCH);
    extract_hist16_k<<<ge, 256>>>(probs);
    select16_k<<<BATCH, 1024>>>();
    dim3 gc(64, BATCH);
    compact_k<<<gc, 256>>>(probs);
    sort_decode_k<<<BATCH, 1024, SEL_CAP * 8>>>(bbox, anchors);
    dim3 gi((CMASK * MWORDS) / 32, BATCH);
    iou_mask_k<<<gi, 1024>>>();
    nms_resolve_k<<<BATCH, 1024, SMEM_RESOLVE>>>(out);
}

// round 6
// speedup vs baseline: 1.2290x; 1.0488x over previous
#include <cuda_runtime.h>
#include <math.h>

#define BATCH 8
#define NN 262144
#define PRE 6000
#define PROP 1000
#define SEL_CAP 8192
#define CMASK 1024
#define MWORDS (CMASK / 32)

// ---------------- scratch ----------------
__device__ int                g_h16[BATCH * 65536];           // zero-init; select16 re-zeros
__device__ unsigned int       g_thr[BATCH];
__device__ int                g_cnt[BATCH];                   // reset by select16
__device__ unsigned long long g_sel[BATCH * SEL_CAP];
__device__ float4             g_boxes[BATCH * PRE];
__device__ unsigned int       g_mask[BATCH * CMASK * MWORDS];

__device__ __forceinline__ unsigned fkey(float f) {
    unsigned u = __float_as_uint(f);
    return u ^ (((unsigned)((int)u >> 31)) | 0x80000000u);
}

// ---------------- pass 1: 16-bit histogram of score keys ----------------
__global__ void extract_hist16_k(const float* __restrict__ probs) {
    int tid = threadIdx.x, b = blockIdx.y;
    const float4* p4 = (const float4*)probs + (size_t)b * (NN / 2);
    int* h = &g_h16[b * 65536];
    float4 v[4];
    int f0 = blockIdx.x * 1024 + tid;
#pragma unroll
    for (int t = 0; t < 4; t++) v[t] = p4[f0 + t * 256];
#pragma unroll
    for (int t = 0; t < 4; t++) {
        atomicAdd(&h[fkey(v[t].y) >> 16], 1);
        atomicAdd(&h[fkey(v[t].w) >> 16], 1);
    }
}

// ---------------- select threshold bin (parallel suffix scan) ----------------
__global__ void __launch_bounds__(1024, 1) select16_k() {
    __shared__ int part[1024];
    __shared__ int save[64];
    __shared__ int chunkT;
    int tid = threadIdx.x, b = blockIdx.x;
    int* h = &g_h16[b * 65536];
    const int4* h4 = (const int4*)h;

    int s = 0;
#pragma unroll
    for (int q = 0; q < 16; q++) {
        int4 v = h4[tid * 16 + q];
        s += v.x + v.y + v.z + v.w;
    }
    int val = s;
    part[tid] = val;
    __syncthreads();
    for (int off = 1; off < 1024; off <<= 1) {
        int add = (tid + off < 1024) ? part[tid + off] : 0;
        __syncthreads();
        val += add;
        part[tid] = val;
        __syncthreads();
    }
    if (part[tid] >= PRE && (tid == 1023 || part[tid + 1] < PRE)) chunkT = tid;
    __syncthreads();
    int t = chunkT;
    if (tid < 64) save[tid] = h[t * 64 + tid];
    __syncthreads();
    int4 z = make_int4(0, 0, 0, 0);
#pragma unroll
    for (int q = 0; q < 16; q++) ((int4*)h)[tid * 16 + q] = z;
    if (tid == 0) {
        g_cnt[b] = 0;
        int acc = (t < 1023) ? part[t + 1] : 0;
        int bin = 63;
        for (; bin > 0; bin--) {
            int c = save[bin];
            if (acc + c >= PRE) break;
            acc += c;
        }
        g_thr[b] = ((unsigned)(t * 64 + bin)) << 16;
    }
}

// ---------------- compact all keys >= threshold ----------------
__global__ void compact_k(const float* __restrict__ probs) {
    int tid = threadIdx.x, b = blockIdx.y;
    unsigned T = g_thr[b];
    const float4* p4 = (const float4*)probs + (size_t)b * (NN / 2);
    int f0 = blockIdx.x * 2048 + tid;
    float4 v[8];
#pragma unroll
    for (int t = 0; t < 8; t++) v[t] = p4[f0 + t * 256];
#pragma unroll
    for (int t = 0; t < 8; t++) {
        int f = f0 + t * 256;
        unsigned k0 = fkey(v[t].y), k1 = fkey(v[t].w);
        if (k0 >= T) {
            int pos = atomicAdd(&g_cnt[b], 1);
            if (pos < SEL_CAP)
                g_sel[b * SEL_CAP + pos] =
                    (((unsigned long long)(~k0)) << 32) | (unsigned)(f * 2);
        }
        if (k1 >= T) {
            int pos = atomicAdd(&g_cnt[b], 1);
            if (pos < SEL_CAP)
                g_sel[b * SEL_CAP + pos] =
                    (((unsigned long long)(~k1)) << 32) | (unsigned)(f * 2 + 1);
        }
    }
}

// ---------------- shuffle-tier bitonic sort + decode ----------------
__device__ __forceinline__ void cswap(unsigned long long& x, unsigned long long& y, bool up) {
    if ((x > y) == up) { unsigned long long t = x; x = y; y = t; }
}

// in-register j=4,2,1 phases with uniform direction
__device__ __forceinline__ void reg_phases(unsigned long long v[8], bool up) {
#pragma unroll
    for (int j = 4; j > 0; j >>= 1) {
#pragma unroll
        for (int e = 0; e < 8; e++) {
            int ex = e ^ j;
            if (ex > e) cswap(v[e], v[ex], up);
        }
    }
}

// intra-warp shuffle phases: j from jhi down to 8 (xor distance j/8 lanes)
__device__ __forceinline__ void shfl_phases(unsigned long long v[8], int jhi, bool up, int tid) {
    for (int m = jhi >> 3; m >= 1; m >>= 1) {
        bool lower = ((tid & m) == 0);
        bool takeMin = (lower == up);
#pragma unroll
        for (int e = 0; e < 8; e++) {
            unsigned long long o = __shfl_xor_sync(0xFFFFFFFFu, v[e], m);
            unsigned long long mn = (v[e] < o) ? v[e] : o;
            unsigned long long mx = (v[e] < o) ? o : v[e];
            v[e] = takeMin ? mn : mx;
        }
    }
}

__global__ void __launch_bounds__(1024, 1)
sort_decode_k(const float* __restrict__ bbox, const float* __restrict__ anchors) {
    extern __shared__ unsigned long long a[];
    int tid = threadIdx.x, b = blockIdx.x;
    int cnt = g_cnt[b];
    if (cnt > SEL_CAP) cnt = SEL_CAP;
    const unsigned long long* gs = &g_sel[b * SEL_CAP];

    unsigned long long v[8];
    int base = tid * 8;
#pragma unroll
    for (int e = 0; e < 8; e++)
        v[e] = (base + e < cnt) ? gs[base + e] : 0xFFFFFFFFFFFFFFFFull;

    // k = 2,4,8: fully in-register (direction varies per element)
#pragma unroll
    for (int k = 2; k <= 8; k <<= 1) {
#pragma unroll
        for (int j = k >> 1; j > 0; j >>= 1) {
#pragma unroll
            for (int e = 0; e < 8; e++) {
                int ex = e ^ j;
                if (ex > e) cswap(v[e], v[ex], ((base + e) & k) == 0);
            }
        }
    }

    // k = 16..256: shuffle + register phases, no smem
#pragma unroll
    for (int k = 16; k <= 256; k <<= 1) {
        bool up = ((base & k) == 0);
        shfl_phases(v, k >> 1, up, tid);
        reg_phases(v, up);
    }

    // k = 512..8192: smem phases for j>=256, then shfl + register
    for (int k = 512; k <= SEL_CAP; k <<= 1) {
#pragma unroll
        for (int e = 0; e < 8; e++) a[base + e] = v[e];
        __syncthreads();
        for (int j = k >> 1; j >= 256; j >>= 1) {
#pragma unroll 4
            for (int m = tid; m < SEL_CAP / 2; m += 1024) {
                int i = ((m & ~(j - 1)) << 1) | (m & (j - 1));
                int ix = i | j;
                unsigned long long x = a[i], y = a[ix];
                if ((x > y) == ((i & k) == 0)) { a[i] = y; a[ix] = x; }
            }
            __syncthreads();
        }
#pragma unroll
        for (int e = 0; e < 8; e++) v[e] = a[base + e];
        __syncthreads();
        bool up = ((base & k) == 0);
        shfl_phases(v, 128, up, tid);
        reg_phases(v, up);
    }

    // stage sorted keys to smem for decode indexing
#pragma unroll
    for (int e = 0; e < 8; e++) a[base + e] = v[e];
    __syncthreads();

    for (int r = tid; r < PRE; r += 1024) {
        unsigned idx = (unsigned)a[r];
        float4 A = ((const float4*)anchors)[(size_t)b * NN + idx];
        float4 D = ((const float4*)bbox)[(size_t)b * NN + idx];
        float y1 = A.x, x1 = A.y, y2 = A.z, x2 = A.w;
        float h = __fsub_rn(y2, y1), w = __fsub_rn(x2, x1);
        float cy = __fadd_rn(y1, __fmul_rn(0.5f, h));
        float cx = __fadd_rn(x1, __fmul_rn(0.5f, w));
        float d0 = __fmul_rn(D.x, 0.1f), d1 = __fmul_rn(D.y, 0.1f);
        float d2 = __fmul_rn(D.z, 0.2f), d3 = __fmul_rn(D.w, 0.2f);
        cy = __fadd_rn(cy, __fmul_rn(d0, h));
        cx = __fadd_rn(cx, __fmul_rn(d1, w));
        h = __fmul_rn(h, expf(d2));
        w = __fmul_rn(w, expf(d3));
        float ny1 = __fsub_rn(cy, __fmul_rn(0.5f, h));
        float nx1 = __fsub_rn(cx, __fmul_rn(0.5f, w));
        float ny2 = __fadd_rn(cy, __fmul_rn(0.5f, h));
        float nx2 = __fadd_rn(cx, __fmul_rn(0.5f, w));
        ny1 = fminf(fmaxf(ny1, 0.f), 1.f);
        nx1 = fminf(fmaxf(nx1, 0.f), 1.f);
        ny2 = fminf(fmaxf(ny2, 0.f), 1.f);
        nx2 = fminf(fmaxf(nx2, 0.f), 1.f);
        g_boxes[b * PRE + r] = make_float4(ny1, nx1, ny2, nx2);
    }
}

// ---------------- suppression IoU (exact, used by fallback) ----------------
__device__ __forceinline__ int suppresses(float4 s, float sArea, float4 c) {
    float iy1 = fmaxf(c.x, s.x), ix1 = fmaxf(c.y, s.y);
    float iy2 = fminf(c.z, s.z), ix2 = fminf(c.w, s.w);
    float ih = fmaxf(__fsub_rn(iy2, iy1), 0.f);
    float iw = fmaxf(__fsub_rn(ix2, ix1), 0.f);
    float inter = __fmul_rn(ih, iw);
    float areaC = __fmul_rn(__fsub_rn(c.z, c.x), __fsub_rn(c.w, c.y));
    float uni = __fsub_rn(__fadd_rn(sArea, areaC), inter);
    float iou = __fdiv_rn(inter, fmaxf(uni, 1e-10f));
    return iou > 0.7f;
}

// ---------------- IoU bit-matrix: warp-per-word, lane-per-pair, ballot ----------------
__global__ void iou_mask_k() {
    int b = blockIdx.y;
    int warpId = threadIdx.x >> 5, lane = threadIdx.x & 31;
    int W = blockIdx.x * 32 + warpId;
    int i = W >> 5;
    int wj = W & (MWORDS - 1);
    int j = wj * 32 + lane;
    const float4* bx = &g_boxes[(size_t)b * PRE];
    float4 s = bx[i];
    int bit = 0;
    if (j > i) {
        float4 c = bx[j];
        float iy1 = fmaxf(c.x, s.x), ix1 = fmaxf(c.y, s.y);
        float iy2 = fminf(c.z, s.z), ix2 = fminf(c.w, s.w);
        if (iy2 > iy1 && ix2 > ix1) {
            float ih = __fsub_rn(iy2, iy1);
            float iw = __fsub_rn(ix2, ix1);
            float inter = __fmul_rn(ih, iw);
            float sA = __fmul_rn(__fsub_rn(s.z, s.x), __fsub_rn(s.w, s.y));
            float cA = __fmul_rn(__fsub_rn(c.z, c.x), __fsub_rn(c.w, c.y));
            float uni = __fsub_rn(__fadd_rn(sA, cA), inter);
            float iou = __fdiv_rn(inter, fmaxf(uni, 1e-10f));
            bit = (iou > 0.7f);
        }
    }
    unsigned word = __ballot_sync(0xFFFFFFFFu, bit);
    if (lane == 0) g_mask[((size_t)b * CMASK + i) * MWORDS + wj] = word;
}

// ---------------- block-sequential parallel NMS resolve ----------------
#define SMEM_RESOLVE (CMASK * MWORDS * 4 + 32 * 4 + 32 * 4 + 33 * 4 + PROP * 4 + 32)

__global__ void __launch_bounds__(1024, 1) nms_resolve_k(float* __restrict__ out) {
    extern __shared__ unsigned sm[];
    unsigned* smask  = sm;
    unsigned* supArr = sm + CMASK * MWORDS;
    unsigned* awords = supArr + 32;
    int* wpref       = (int*)(awords + 32);
    int* selids      = wpref + 33;

    int tid = threadIdx.x, b = blockIdx.x;

    const unsigned* gm = &g_mask[(size_t)b * CMASK * MWORDS];
#pragma unroll
    for (int i = tid; i < CMASK * MWORDS; i += 1024) smask[i] = gm[i];
    if (tid < 32) { supArr[tid] = 0; awords[tid] = 0xFFFFFFFFu; }
    __syncthreads();

    for (int B = 0; B < MWORDS; B++) {
        unsigned contrib = 0;
        if (tid < B * 32) {
            if ((awords[tid >> 5] >> (tid & 31)) & 1u)
                contrib = smask[tid * MWORDS + B];
        }
        contrib = __reduce_or_sync(0xFFFFFFFFu, contrib);
        if ((tid & 31) == 0 && contrib) atomicOr(&supArr[B], contrib);
        __syncthreads();
        if (tid < 32) {
            unsigned myrow = smask[(B * 32 + tid) * MWORDS + B];
            unsigned aliveB = ~supArr[B];
            unsigned candm = __ballot_sync(0xFFFFFFFFu, myrow != 0);
            while (true) {
                unsigned act = candm & aliveB;
                if (!act) break;
                int bs = __ffs(act) - 1;
                unsigned rowW = __shfl_sync(0xFFFFFFFFu, myrow, bs);
                aliveB &= ~rowW;
                candm &= ~(1u << bs);
            }
            if (tid == 0) awords[B] = aliveB;
        }
        __syncthreads();
    }

    if (tid == 0) {
        int acc = 0;
        for (int wq = 0; wq < 32; wq++) { wpref[wq] = acc; acc += __popc(awords[wq]); }
        wpref[32] = acc;
    }
    __syncthreads();
    if (tid < CMASK) {
        unsigned wv = awords[tid >> 5];
        if ((wv >> (tid & 31)) & 1u) {
            int rank = wpref[tid >> 5] + __popc(wv & ((1u << (tid & 31)) - 1u));
            if (rank < PROP) selids[rank] = tid;
        }
    }
    __syncthreads();
    int k = wpref[32];
    if (k > PROP) k = PROP;

    if (k < PROP) {
        float4 mysel = make_float4(0.f, 0.f, 0.f, 0.f);
        float myarea = 0.f;
        if (tid < k) {
            mysel = g_boxes[b * PRE + selids[tid]];
            myarea = __fmul_rn(__fsub_rn(mysel.z, mysel.x), __fsub_rn(mysel.w, mysel.y));
        }
        __syncthreads();
        for (int cand = CMASK; cand < PRE; cand++) {
            float4 c = g_boxes[b * PRE + cand];
            int pred = 0;
            if (tid < k) pred = suppresses(mysel, myarea, c);
            int rej = __syncthreads_or(pred);
            if (!rej) {
                if (tid == k) {
                    mysel = c;
                    myarea = __fmul_rn(__fsub_rn(c.z, c.x), __fsub_rn(c.w, c.y));
                }
                if (tid == 0) selids[k] = cand;
                k++;
                if (k == PROP) break;
            }
        }
        __syncthreads();
    }

    float4* outp = (float4*)out + (size_t)b * PROP;
    if (tid < PROP) {
        if (tid < k) outp[tid] = g_boxes[b * PRE + selids[tid]];
        else         outp[tid] = make_float4(0.f, 0.f, 0.f, 0.f);
    }
}

// ---------------- launch ----------------
extern "C" void kernel_launch(void* const* d_in, const int* in_sizes, int n_in,
                              void* d_out, int out_size) {
    const float* probs   = (const float*)d_in[0];
    const float* bbox    = (const float*)d_in[1];
    const float* anchors = (const float*)d_in[2];
    float* out = (float*)d_out;

    cudaFuncSetAttribute(sort_decode_k, cudaFuncAttributeMaxDynamicSharedMemorySize, SEL_CAP * 8);
    cudaFuncSetAttribute(nms_resolve_k, cudaFuncAttributeMaxDynamicSharedMemorySize, SMEM_RESOLVE);

    dim3 ge(128, BATCH);
    extract_hist16_k<<<ge, 256>>>(probs);
    select16_k<<<BATCH, 1024>>>();
    dim3 gc(64, BATCH);
    compact_k<<<gc, 256>>>(probs);
    sort_decode_k<<<BATCH, 1024, SEL_CAP * 8>>>(bbox, anchors);
    dim3 gi((CMASK * MWORDS) / 32, BATCH);
    iou_mask_k<<<gi, 1024>>>();
    nms_resolve_k<<<BATCH, 1024, SMEM_RESOLVE>>>(out);
}

// round 7
// speedup vs baseline: 1.3754x; 1.1192x over previous
#include <cuda_runtime.h>
#include <math.h>

#define BATCH 8
#define NN 262144
#define PRE 6000
#define PROP 1000
#define SEL_CAP 8192
#define CMASK 1024
#define MWORDS (CMASK / 32)

// ---------------- scratch ----------------
__device__ int                g_h16[BATCH * 65536];           // zero-init; select16 re-zeros
__device__ unsigned int       g_thr[BATCH];
__device__ int                g_cnt[BATCH];                   // reset by select16
__device__ unsigned long long g_sel[BATCH * SEL_CAP];
__device__ float4             g_boxes[BATCH * PRE];
__device__ unsigned int       g_mask[BATCH * MWORDS * CMASK]; // TRANSPOSED: [b][wj][i]

__device__ __forceinline__ unsigned fkey(float f) {
    unsigned u = __float_as_uint(f);
    return u ^ (((unsigned)((int)u >> 31)) | 0x80000000u);
}

// ---------------- pass 1: 16-bit histogram of score keys ----------------
__global__ void extract_hist16_k(const float* __restrict__ probs) {
    int tid = threadIdx.x, b = blockIdx.y;
    const float4* p4 = (const float4*)probs + (size_t)b * (NN / 2);
    int* h = &g_h16[b * 65536];
    float4 v[4];
    int f0 = blockIdx.x * 1024 + tid;
#pragma unroll
    for (int t = 0; t < 4; t++) v[t] = p4[f0 + t * 256];
#pragma unroll
    for (int t = 0; t < 4; t++) {
        atomicAdd(&h[fkey(v[t].y) >> 16], 1);
        atomicAdd(&h[fkey(v[t].w) >> 16], 1);
    }
}

// ---------------- select threshold bin (parallel suffix scan) ----------------
__global__ void __launch_bounds__(1024, 1) select16_k() {
    __shared__ int part[1024];
    __shared__ int save[64];
    __shared__ int chunkT;
    int tid = threadIdx.x, b = blockIdx.x;
    int* h = &g_h16[b * 65536];
    const int4* h4 = (const int4*)h;

    int s = 0;
#pragma unroll
    for (int q = 0; q < 16; q++) {
        int4 v = h4[tid * 16 + q];
        s += v.x + v.y + v.z + v.w;
    }
    int val = s;
    part[tid] = val;
    __syncthreads();
    for (int off = 1; off < 1024; off <<= 1) {
        int add = (tid + off < 1024) ? part[tid + off] : 0;
        __syncthreads();
        val += add;
        part[tid] = val;
        __syncthreads();
    }
    if (part[tid] >= PRE && (tid == 1023 || part[tid + 1] < PRE)) chunkT = tid;
    __syncthreads();
    int t = chunkT;
    if (tid < 64) save[tid] = h[t * 64 + tid];
    __syncthreads();
    int4 z = make_int4(0, 0, 0, 0);
#pragma unroll
    for (int q = 0; q < 16; q++) ((int4*)h)[tid * 16 + q] = z;
    if (tid == 0) {
        g_cnt[b] = 0;
        int acc = (t < 1023) ? part[t + 1] : 0;
        int bin = 63;
        for (; bin > 0; bin--) {
            int c = save[bin];
            if (acc + c >= PRE) break;
            acc += c;
        }
        g_thr[b] = ((unsigned)(t * 64 + bin)) << 16;
    }
}

// ---------------- compact all keys >= threshold ----------------
__global__ void compact_k(const float* __restrict__ probs) {
    int tid = threadIdx.x, b = blockIdx.y;
    unsigned T = g_thr[b];
    const float4* p4 = (const float4*)probs + (size_t)b * (NN / 2);
    int f0 = blockIdx.x * 2048 + tid;
    float4 v[8];
#pragma unroll
    for (int t = 0; t < 8; t++) v[t] = p4[f0 + t * 256];
#pragma unroll
    for (int t = 0; t < 8; t++) {
        int f = f0 + t * 256;
        unsigned k0 = fkey(v[t].y), k1 = fkey(v[t].w);
        if (k0 >= T) {
            int pos = atomicAdd(&g_cnt[b], 1);
            if (pos < SEL_CAP)
                g_sel[b * SEL_CAP + pos] =
                    (((unsigned long long)(~k0)) << 32) | (unsigned)(f * 2);
        }
        if (k1 >= T) {
            int pos = atomicAdd(&g_cnt[b], 1);
            if (pos < SEL_CAP)
                g_sel[b * SEL_CAP + pos] =
                    (((unsigned long long)(~k1)) << 32) | (unsigned)(f * 2 + 1);
        }
    }
}

// ---------------- bitonic helpers ----------------
__device__ __forceinline__ void cswap(unsigned long long& x, unsigned long long& y, bool up) {
    if ((x > y) == up) { unsigned long long t = x; x = y; y = t; }
}

// ---------------- sortA: 2 blocks/batch, each sorts 4096 (asc iff half==0) ----------------
__global__ void __launch_bounds__(1024, 1) sortA_k() {
    __shared__ unsigned long long a[4096];
    int tid = threadIdx.x, h = blockIdx.x, b = blockIdx.y;
    int cnt = g_cnt[b];
    if (cnt > SEL_CAP) cnt = SEL_CAP;
    unsigned long long* gs = &g_sel[b * SEL_CAP + h * 4096];
    int lim = cnt - h * 4096;

    unsigned long long v[4];
    int base = tid * 4;
#pragma unroll
    for (int e = 0; e < 4; e++)
        v[e] = (base + e < lim) ? gs[base + e] : 0xFFFFFFFFFFFFFFFFull;

    bool dir = (h == 0);   // this block sorts ascending iff true

    // k=2,4: in-register
#pragma unroll
    for (int k = 2; k <= 4; k <<= 1) {
#pragma unroll
        for (int j = k >> 1; j > 0; j >>= 1) {
#pragma unroll
            for (int e = 0; e < 4; e++) {
                int ex = e ^ j;
                if (ex > e) cswap(v[e], v[ex], (((base + e) & k) == 0) == dir);
            }
        }
    }

    // k=8..128: shuffle tier (warp covers 128 elements; j=4..64 via shfl, j<=2 reg)
#pragma unroll
    for (int k = 8; k <= 128; k <<= 1) {
        bool up = (((base & k) == 0) == dir);
        for (int m = k >> 3; m >= 1; m >>= 1) {
            bool takeMin = (((tid & m) == 0) == up);
#pragma unroll
            for (int e = 0; e < 4; e++) {
                unsigned long long o = __shfl_xor_sync(0xFFFFFFFFu, v[e], m);
                unsigned long long mn = (v[e] < o) ? v[e] : o;
                unsigned long long mx = (v[e] < o) ? o : v[e];
                v[e] = takeMin ? mn : mx;
            }
        }
#pragma unroll
        for (int j = 2; j > 0; j >>= 1) {
#pragma unroll
            for (int e = 0; e < 4; e++) {
                int ex = e ^ j;
                if (ex > e) cswap(v[e], v[ex], up);
            }
        }
    }

    // k=256..4096: smem for j>=128, then shfl (j=64..4) + reg (j=2,1)
    for (int k = 256; k <= 4096; k <<= 1) {
#pragma unroll
        for (int e = 0; e < 4; e++) a[base + e] = v[e];
        __syncthreads();
        for (int j = k >> 1; j >= 128; j >>= 1) {
#pragma unroll 2
            for (int m2 = tid; m2 < 2048; m2 += 1024) {
                int i = ((m2 & ~(j - 1)) << 1) | (m2 & (j - 1));
                int ix = i | j;
                unsigned long long x = a[i], y = a[ix];
                if ((x > y) == (((i & k) == 0) == dir)) { a[i] = y; a[ix] = x; }
            }
            __syncthreads();
        }
#pragma unroll
        for (int e = 0; e < 4; e++) v[e] = a[base + e];
        __syncthreads();
        bool up = (((base & k) == 0) == dir);
        for (int m = 16; m >= 1; m >>= 1) {
            bool takeMin = (((tid & m) == 0) == up);
#pragma unroll
            for (int e = 0; e < 4; e++) {
                unsigned long long o = __shfl_xor_sync(0xFFFFFFFFu, v[e], m);
                unsigned long long mn = (v[e] < o) ? v[e] : o;
                unsigned long long mx = (v[e] < o) ? o : v[e];
                v[e] = takeMin ? mn : mx;
            }
        }
#pragma unroll
        for (int j = 2; j > 0; j >>= 1) {
#pragma unroll
            for (int e = 0; e < 4; e++) {
                int ex = e ^ j;
                if (ex > e) cswap(v[e], v[ex], up);
            }
        }
    }

#pragma unroll
    for (int e = 0; e < 4; e++) gs[base + e] = v[e];
}

// ---------------- sortB: final k=8192 merge (all-ascending) + decode ----------------
__global__ void __launch_bounds__(1024, 1)
sortB_decode_k(const float* __restrict__ bbox, const float* __restrict__ anchors) {
    extern __shared__ unsigned long long a[];
    int tid = threadIdx.x, b = blockIdx.x;
    const unsigned long long* gs = &g_sel[b * SEL_CAP];
    for (int i = tid; i < SEL_CAP; i += 1024) a[i] = gs[i];
    __syncthreads();

    // k=8192 stage: direction ascending everywhere. j=4096..256 in smem.
    for (int j = 4096; j >= 256; j >>= 1) {
#pragma unroll 4
        for (int m = tid; m < SEL_CAP / 2; m += 1024) {
            int i = ((m & ~(j - 1)) << 1) | (m & (j - 1));
            int ix = i | j;
            unsigned long long x = a[i], y = a[ix];
            if (x > y) { a[i] = y; a[ix] = x; }
        }
        __syncthreads();
    }
    // j=128..8 shuffle, j=4,2,1 register (8 elems/thread, up=true)
    unsigned long long v[8];
    int base = tid * 8;
#pragma unroll
    for (int e = 0; e < 8; e++) v[e] = a[base + e];
    __syncthreads();
    for (int m = 16; m >= 1; m >>= 1) {
        bool takeMin = ((tid & m) == 0);
#pragma unroll
        for (int e = 0; e < 8; e++) {
            unsigned long long o = __shfl_xor_sync(0xFFFFFFFFu, v[e], m);
            unsigned long long mn = (v[e] < o) ? v[e] : o;
            unsigned long long mx = (v[e] < o) ? o : v[e];
            v[e] = takeMin ? mn : mx;
        }
    }
#pragma unroll
    for (int j = 4; j > 0; j >>= 1) {
#pragma unroll
        for (int e = 0; e < 8; e++) {
            int ex = e ^ j;
            if (ex > e) cswap(v[e], v[ex], true);
        }
    }
#pragma unroll
    for (int e = 0; e < 8; e++) a[base + e] = v[e];
    __syncthreads();

    // decode top PRE boxes
    for (int r = tid; r < PRE; r += 1024) {
        unsigned idx = (unsigned)a[r];
        float4 A = ((const float4*)anchors)[(size_t)b * NN + idx];
        float4 D = ((const float4*)bbox)[(size_t)b * NN + idx];
        float y1 = A.x, x1 = A.y, y2 = A.z, x2 = A.w;
        float h = __fsub_rn(y2, y1), w = __fsub_rn(x2, x1);
        float cy = __fadd_rn(y1, __fmul_rn(0.5f, h));
        float cx = __fadd_rn(x1, __fmul_rn(0.5f, w));
        float d0 = __fmul_rn(D.x, 0.1f), d1 = __fmul_rn(D.y, 0.1f);
        float d2 = __fmul_rn(D.z, 0.2f), d3 = __fmul_rn(D.w, 0.2f);
        cy = __fadd_rn(cy, __fmul_rn(d0, h));
        cx = __fadd_rn(cx, __fmul_rn(d1, w));
        h = __fmul_rn(h, expf(d2));
        w = __fmul_rn(w, expf(d3));
        float ny1 = __fsub_rn(cy, __fmul_rn(0.5f, h));
        float nx1 = __fsub_rn(cx, __fmul_rn(0.5f, w));
        float ny2 = __fadd_rn(cy, __fmul_rn(0.5f, h));
        float nx2 = __fadd_rn(cx, __fmul_rn(0.5f, w));
        ny1 = fminf(fmaxf(ny1, 0.f), 1.f);
        nx1 = fminf(fmaxf(nx1, 0.f), 1.f);
        ny2 = fminf(fmaxf(ny2, 0.f), 1.f);
        nx2 = fminf(fmaxf(nx2, 0.f), 1.f);
        g_boxes[b * PRE + r] = make_float4(ny1, nx1, ny2, nx2);
    }
}

// ---------------- suppression IoU (exact, used by fallback) ----------------
__device__ __forceinline__ int suppresses(float4 s, float sArea, float4 c) {
    float iy1 = fmaxf(c.x, s.x), ix1 = fmaxf(c.y, s.y);
    float iy2 = fminf(c.z, s.z), ix2 = fminf(c.w, s.w);
    float ih = fmaxf(__fsub_rn(iy2, iy1), 0.f);
    float iw = fmaxf(__fsub_rn(ix2, ix1), 0.f);
    float inter = __fmul_rn(ih, iw);
    float areaC = __fmul_rn(__fsub_rn(c.z, c.x), __fsub_rn(c.w, c.y));
    float uni = __fsub_rn(__fadd_rn(sArea, areaC), inter);
    float iou = __fdiv_rn(inter, fmaxf(uni, 1e-10f));
    return iou > 0.7f;
}

// ---------------- IoU bit-matrix (transposed layout [b][wj][i]) ----------------
__global__ void iou_mask_k() {
    int b = blockIdx.y;
    int warpId = threadIdx.x >> 5, lane = threadIdx.x & 31;
    int W = blockIdx.x * 32 + warpId;
    int i = W >> 5;                      // suppressor row
    int wj = W & (MWORDS - 1);
    int j = wj * 32 + lane;              // suppressed candidate
    const float4* bx = &g_boxes[(size_t)b * PRE];
    float4 s = bx[i];
    int bit = 0;
    if (j > i) {
        float4 c = bx[j];
        float iy1 = fmaxf(c.x, s.x), ix1 = fmaxf(c.y, s.y);
        float iy2 = fminf(c.z, s.z), ix2 = fminf(c.w, s.w);
        if (iy2 > iy1 && ix2 > ix1) {
            float ih = __fsub_rn(iy2, iy1);
            float iw = __fsub_rn(ix2, ix1);
            float inter = __fmul_rn(ih, iw);
            float sA = __fmul_rn(__fsub_rn(s.z, s.x), __fsub_rn(s.w, s.y));
            float cA = __fmul_rn(__fsub_rn(c.z, c.x), __fsub_rn(c.w, c.y));
            float uni = __fsub_rn(__fadd_rn(sA, cA), inter);
            float iou = __fdiv_rn(inter, fmaxf(uni, 1e-10f));
            bit = (iou > 0.7f);
        }
    }
    unsigned word = __ballot_sync(0xFFFFFFFFu, bit);
    if (lane == 0) g_mask[((size_t)b * MWORDS + wj) * CMASK + i] = word;
}

// ---------------- block-sequential parallel NMS resolve (conflict-free) ----------------
#define SMEM_RESOLVE (MWORDS * CMASK * 4 + 32 * 4 + 32 * 4 + 33 * 4 + PROP * 4 + 32)

__global__ void __launch_bounds__(1024, 1) nms_resolve_k(float* __restrict__ out) {
    extern __shared__ unsigned sm[];
    unsigned* smask  = sm;                          // [wj][i] transposed
    unsigned* supArr = sm + MWORDS * CMASK;
    unsigned* awords = supArr + 32;
    int* wpref       = (int*)(awords + 32);
    int* selids      = wpref + 33;

    int tid = threadIdx.x, b = blockIdx.x;

    const unsigned* gm = &g_mask[(size_t)b * MWORDS * CMASK];
#pragma unroll
    for (int i = tid; i < MWORDS * CMASK; i += 1024) smask[i] = gm[i];
    if (tid < 32) { supArr[tid] = 0; awords[tid] = 0xFFFFFFFFu; }
    __syncthreads();

    for (int B = 0; B < MWORDS; B++) {
        // cross-block: word B of rows tid (stride-1 in transposed layout)
        unsigned contrib = 0;
        if (tid < B * 32) {
            if ((awords[tid >> 5] >> (tid & 31)) & 1u)
                contrib = smask[B * CMASK + tid];
        }
        contrib = __reduce_or_sync(0xFFFFFFFFu, contrib);
        if ((tid & 31) == 0 && contrib) atomicOr(&supArr[B], contrib);
        __syncthreads();
        // within-block resolution by warp 0 (diagonal words, stride-1)
        if (tid < 32) {
            unsigned myrow = smask[B * CMASK + B * 32 + tid];
            unsigned aliveB = ~supArr[B];
            unsigned candm = __ballot_sync(0xFFFFFFFFu, myrow != 0);
            while (true) {
                unsigned act = candm & aliveB;
                if (!act) break;
                int bs = __ffs(act) - 1;
                unsigned rowW = __shfl_sync(0xFFFFFFFFu, myrow, bs);
                aliveB &= ~rowW;
                candm &= ~(1u << bs);
            }
            if (tid == 0) awords[B] = aliveB;
        }
        __syncthreads();
    }

    if (tid == 0) {
        int acc = 0;
        for (int wq = 0; wq < 32; wq++) { wpref[wq] = acc; acc += __popc(awords[wq]); }
        wpref[32] = acc;
    }
    __syncthreads();
    if (tid < CMASK) {
        unsigned wv = awords[tid >> 5];
        if ((wv >> (tid & 31)) & 1u) {
            int rank = wpref[tid >> 5] + __popc(wv & ((1u << (tid & 31)) - 1u));
            if (rank < PROP) selids[rank] = tid;
        }
    }
    __syncthreads();
    int k = wpref[32];
    if (k > PROP) k = PROP;

    if (k < PROP) {
        float4 mysel = make_float4(0.f, 0.f, 0.f, 0.f);
        float myarea = 0.f;
        if (tid < k) {
            mysel = g_boxes[b * PRE + selids[tid]];
            myarea = __fmul_rn(__fsub_rn(mysel.z, mysel.x), __fsub_rn(mysel.w, mysel.y));
        }
        __syncthreads();
        for (int cand = CMASK; cand < PRE; cand++) {
            float4 c = g_boxes[b * PRE + cand];
            int pred = 0;
            if (tid < k) pred = suppresses(mysel, myarea, c);
            int rej = __syncthreads_or(pred);
            if (!rej) {
                if (tid == k) {
                    mysel = c;
                    myarea = __fmul_rn(__fsub_rn(c.z, c.x), __fsub_rn(c.w, c.y));
                }
                if (tid == 0) selids[k] = cand;
                k++;
                if (k == PROP) break;
            }
        }
        __syncthreads();
    }

    float4* outp = (float4*)out + (size_t)b * PROP;
    if (tid < PROP) {
        if (tid < k) outp[tid] = g_boxes[b * PRE + selids[tid]];
        else         outp[tid] = make_float4(0.f, 0.f, 0.f, 0.f);
    }
}

// ---------------- launch ----------------
extern "C" void kernel_launch(void* const* d_in, const int* in_sizes, int n_in,
                              void* d_out, int out_size) {
    const float* probs   = (const float*)d_in[0];
    const float* bbox    = (const float*)d_in[1];
    const float* anchors = (const float*)d_in[2];
    float* out = (float*)d_out;

    cudaFuncSetAttribute(sortB_decode_k, cudaFuncAttributeMaxDynamicSharedMemorySize, SEL_CAP * 8);
    cudaFuncSetAttribute(nms_resolve_k,  cudaFuncAttributeMaxDynamicSharedMemorySize, SMEM_RESOLVE);

    dim3 ge(128, BATCH);
    extract_hist16_k<<<ge, 256>>>(probs);
    select16_k<<<BATCH, 1024>>>();
    dim3 gc(64, BATCH);
    compact_k<<<gc, 256>>>(probs);
    dim3 ga(2, BATCH);
    sortA_k<<<ga, 1024>>>();
    sortB_decode_k<<<BATCH, 1024, SEL_CAP * 8>>>(bbox, anchors);
    dim3 gi((CMASK * MWORDS) / 32, BATCH);
    iou_mask_k<<<gi, 1024>>>();
    nms_resolve_k<<<BATCH, 1024, SMEM_RESOLVE>>>(out);
}